// round 8
// baseline (speedup 1.0000x reference)
#include <cuda_runtime.h>
#include <math.h>

#define NN    8192
#define HN    4096
#define QN    2048
#define MODES 16
#define ROWS  4096          /* BATCH*CH */
#define KSPL  16            /* forward m-splits */
#define MSPL  128           /* m per split = QN/KSPL */

/* fwd combo smem: [cls][m][row], row-stride T, class-stride S (floats) */
#define CMB_T 68            /* 64 rows + pad; T mod 32 = 4, T mod 4 = 0 */
#define CMB_S 2184          /* 32*68+8;      S mod 32 = 8, S mod 4 = 0 */

// Scratch (__device__ globals: allocation-free rule)
__device__ float g_FBf[QN*32];             // fwd basis, grouped, x0.5 at m=0
__device__ float g_FBi[QN*32];             // inv basis, grouped
__device__ float g_partial[KSPL*ROWS*32];  // fwd partial sums (8 MB)
__device__ float g_CS[ROWS*32];            // reduced fwd sums (+boundary)
__device__ float g_C2[ROWS*32];            // irfft coefs, grouped A/B
__device__ float g_WrT[MODES*4096];        // weights transposed: [k][i*64+o]
__device__ float g_WiT[MODES*4096];

// Grouped column layout c' = 0..31:
//   j = c'&7, odd = (c'>>3)&1, k = 2j+odd
//   c' 0..7: cos even k   8..15: cos odd   16..23: sin even   24..31: sin odd
__global__ void init_basis() {
    int idx = blockIdx.x * blockDim.x + threadIdx.x;
    if (idx >= QN * 32) return;
    int m = idx >> 5, c = idx & 31;
    int j = c & 7;
    int kk = 2 * j + ((c >> 3) & 1);
    int t = (kk * m) & (NN - 1);
    float a = (float)t * (1.0f / (float)HN);
    float v = (c < 16) ? cospif(a) : sinpif(a);
    g_FBi[idx] = v;
    g_FBf[idx] = (m == 0) ? 0.5f * v : v;   // m=0 quartet double-counts x[0],x[4096]
}
__global__ void init_wr(const float* __restrict__ wr) {
    int idx = blockIdx.x * blockDim.x + threadIdx.x;
    if (idx >= MODES * 4096) return;
    g_WrT[(idx & 15) * 4096 + (idx >> 4)] = wr[idx];
}
__global__ void init_wi(const float* __restrict__ wi) {
    int idx = blockIdx.x * blockDim.x + threadIdx.x;
    if (idx >= MODES * 4096) return;
    g_WiT[(idx & 15) * 4096 + (idx >> 4)] = wi[idx];
}

// ---------------------------------------------------------------------------
// Forward (folded): CS[row][c'] = sum_m combo_{cls}[row][m] * FBf[m][c']
// 64 rows/block, 64 threads, thread tile 8r x 4c. Inner: 3x LDS.128 + 32 FFMA.
// Quartet {m, 4096-m, 4096+m, (8192-m)&8191} -> 4 class combos.
// ---------------------------------------------------------------------------
__global__ __launch_bounds__(64) void fwd_dft(const float* __restrict__ x) {
    __shared__ float  cmb[4 * CMB_S];     // 34.9 KB
    __shared__ float4 bs[32][8];          // 4 KB

    const int tid  = threadIdx.x;
    const int row0 = blockIdx.x * 64;
    const int ms0  = blockIdx.y * MSPL;
    const int tr   = tid >> 3;            // 0..7  -> rows 8*tr..8*tr+7
    const int tc   = tid & 7;             // 0..7  -> cols 4*tc..4*tc+3
    const int cls  = tc >> 1;             // 0..3

    float acc[8][4];
    #pragma unroll
    for (int j = 0; j < 8; j++)
        #pragma unroll
        for (int q = 0; q < 4; q++) acc[j][q] = 0.f;

    for (int ch = 0; ch < 4; ch++) {
        const int m0 = ms0 + ch * 32;

        // stage combos: thread (row, g) covers m = g + 8*jj; STS banks 4g+row
        // distinct across warp -> conflict-free.
        #pragma unroll
        for (int i = 0; i < 8; i++) {
            int q   = tid + i * 64;
            int row = q >> 3;
            int g   = q & 7;
            const float* xr = x + (size_t)(row0 + row) * NN;
            #pragma unroll
            for (int jj = 0; jj < 4; jj++) {
                int mi = g + 8 * jj;
                int mm = m0 + mi;
                float v0 = xr[mm];
                float v1 = xr[HN - mm];
                float v2 = xr[HN + mm];
                float v3 = xr[(NN - mm) & (NN - 1)];
                float p = v0 + v3, q2 = v0 - v3;
                float r = v1 + v2, s  = v2 - v1;
                float* base = cmb + mi * CMB_T + row;
                base[0 * CMB_S] = p + r;    // even-cos
                base[1 * CMB_S] = p - r;    // odd-cos
                base[2 * CMB_S] = q2 + s;   // even-sin
                base[3 * CMB_S] = q2 - s;   // odd-sin
            }
        }
        // stage basis tile (32 m x 32 c)
        #pragma unroll
        for (int i = 0; i < 4; i++) {
            int q  = tid + i * 64;
            int k  = q >> 3;
            int cq = q & 7;
            bs[k][cq] = *(const float4*)(g_FBf + (size_t)(m0 + k) * 32 + 4 * cq);
        }
        __syncthreads();

        const float* cbase = cmb + cls * CMB_S + 8 * tr;
        #pragma unroll
        for (int m = 0; m < 32; m++) {
            float4 xa = *(const float4*)(cbase + m * CMB_T);      // rows 8tr..+3
            float4 xb = *(const float4*)(cbase + m * CMB_T + 4);  // rows +4..+7
            float4 bv = bs[m][tc];
            acc[0][0] += xa.x * bv.x; acc[0][1] += xa.x * bv.y;
            acc[0][2] += xa.x * bv.z; acc[0][3] += xa.x * bv.w;
            acc[1][0] += xa.y * bv.x; acc[1][1] += xa.y * bv.y;
            acc[1][2] += xa.y * bv.z; acc[1][3] += xa.y * bv.w;
            acc[2][0] += xa.z * bv.x; acc[2][1] += xa.z * bv.y;
            acc[2][2] += xa.z * bv.z; acc[2][3] += xa.z * bv.w;
            acc[3][0] += xa.w * bv.x; acc[3][1] += xa.w * bv.y;
            acc[3][2] += xa.w * bv.z; acc[3][3] += xa.w * bv.w;
            acc[4][0] += xb.x * bv.x; acc[4][1] += xb.x * bv.y;
            acc[4][2] += xb.x * bv.z; acc[4][3] += xb.x * bv.w;
            acc[5][0] += xb.y * bv.x; acc[5][1] += xb.y * bv.y;
            acc[5][2] += xb.y * bv.z; acc[5][3] += xb.y * bv.w;
            acc[6][0] += xb.z * bv.x; acc[6][1] += xb.z * bv.y;
            acc[6][2] += xb.z * bv.z; acc[6][3] += xb.z * bv.w;
            acc[7][0] += xb.w * bv.x; acc[7][1] += xb.w * bv.y;
            acc[7][2] += xb.w * bv.z; acc[7][3] += xb.w * bv.w;
        }
        __syncthreads();
    }

    #pragma unroll
    for (int j = 0; j < 8; j++) {
        int rg = row0 + 8 * tr + j;
        float4 v = make_float4(acc[j][0], acc[j][1], acc[j][2], acc[j][3]);
        *(float4*)(g_partial + ((size_t)blockIdx.y * ROWS + rg) * 32 + 4 * tc) = v;
    }
}

// ---------------------------------------------------------------------------
// Reduce K-splits + m=2048 boundary term. Fully coalesced.
// ---------------------------------------------------------------------------
__global__ __launch_bounds__(256) void reduce_cs(const float* __restrict__ x) {
    int q = blockIdx.x * blockDim.x + threadIdx.x;
    if (q >= ROWS * 32) return;
    int row = q >> 5, c = q & 31;
    float s = 0.f;
    #pragma unroll
    for (int ks = 0; ks < KSPL; ks++)
        s += g_partial[(size_t)ks * ROWS * 32 + q];
    float xa = x[(size_t)row * NN + QN];
    float xb = x[(size_t)row * NN + 3 * QN];
    int j = c & 7;
    float sg = (j & 1) ? -1.f : 1.f;
    if (c < 8)        s += (xa + xb) * sg;
    else if (c >= 24) s += (xa - xb) * sg;
    g_CS[q] = s;
}

// ---------------------------------------------------------------------------
// Mix: grid (16 k, 16 bg), 256 thr. Weights read directly from transposed
// copy (coalesced LDG, L1/L2-resident) -- no smem staging phase.
// ---------------------------------------------------------------------------
__global__ __launch_bounds__(256) void mix() {
    __shared__ float sXc[256], sXs[256];
    const int k   = blockIdx.x;
    const int bg  = blockIdx.y;
    const int tid = threadIdx.x;

    const int cA = (k & 1) ? 8 + (k >> 1) : (k >> 1);
    const int cS = cA + 16;

    {   // (b_local = tid>>6, i = tid&63)
        int row = (bg * 4 + (tid >> 6)) * 64 + (tid & 63);
        sXc[tid] = g_CS[(size_t)row * 32 + cA];
        sXs[tid] = g_CS[(size_t)row * 32 + cS];
    }
    __syncthreads();

    const int o  = tid & 63;
    const int bl = tid >> 6;
    const float* wrk = g_WrT + (size_t)k * 4096 + o;
    const float* wik = g_WiT + (size_t)k * 4096 + o;

    float cre = 0.f, cim = 0.f;
    #pragma unroll 8
    for (int i = 0; i < 64; i++) {
        float a   = sXc[bl * 64 + i];        // broadcast LDS
        float s   = sXs[bl * 64 + i];
        float wre = __ldg(wrk + i * 64);     // coalesced across lanes
        float wim = __ldg(wik + i * 64);
        cre += a * wre + s * wim;
        cim += a * wim - s * wre;
    }
    const float invN = 1.0f / (float)NN;
    float A  = (k == 0 ? cre : 2.f * cre) * invN;
    float Bc = (k == 0 ? 0.f : -2.f * cim * invN);
    int rowo = (bg * 4 + bl) * 64 + o;
    g_C2[(size_t)rowo * 32 + cA] = A;
    g_C2[(size_t)rowo * 32 + cS] = Bc;
}

// ---------------------------------------------------------------------------
// Inverse (folded): thread owns adjacent n1=2*idx, n2=n1+1 (basis 64 regs).
// Per row: 8 broadcast LDS.128 feed 64 FFMA -> 8 outputs.
// Ascending pairs [n1,n2], [np1,np1+1] are 8B-aligned -> STG.64.
// Descending mirrors start at ODD offsets -> scalar STG.32 (alignment!).
// n=0 wrap writes are exact duplicates (sin basis = 0); idx==0 also emits
// n=2048/6144.
// ---------------------------------------------------------------------------
__global__ __launch_bounds__(256) void inv_dft(float* __restrict__ y) {
    __shared__ float sC[64 * 32];
    const int tid  = threadIdx.x;
    const int row0 = blockIdx.y * 64;
    const int idx  = blockIdx.x * 256 + tid;    // 0..1023
    const int n1   = 2 * idx;
    const int n2   = n1 + 1;

    #pragma unroll
    for (int i = 0; i < 2; i++) {
        int q = tid + i * 256;
        *(float4*)(sC + 4 * q) = *(const float4*)(g_C2 + (size_t)row0 * 32 + 4 * q);
    }

    float b1[32], b2[32];
    #pragma unroll
    for (int i = 0; i < 8; i++) {
        float4 v = *(const float4*)(g_FBi + (size_t)n1 * 32 + 4 * i);
        b1[4*i+0] = v.x; b1[4*i+1] = v.y; b1[4*i+2] = v.z; b1[4*i+3] = v.w;
        float4 u = *(const float4*)(g_FBi + (size_t)n2 * 32 + 4 * i);
        b2[4*i+0] = u.x; b2[4*i+1] = u.y; b2[4*i+2] = u.z; b2[4*i+3] = u.w;
    }
    __syncthreads();

    const int np1   = HN + n1;                  // even: STG.64 ok
    const int nm1   = HN - n1;                  // even base, scalar writes
    const int nm2   = HN - n2;                  // odd
    const int nrev1 = (NN - n1) & (NN - 1);     // 0 when idx==0 (dup, benign)
    const int nrev2 = NN - n2;                  // odd

    for (int r = 0; r < 64; r++) {
        float cf[32];
        const float* cp = sC + r * 32;
        #pragma unroll
        for (int i = 0; i < 8; i++) {
            float4 v = *(const float4*)(cp + 4 * i);   // broadcast LDS.128
            cf[4*i+0] = v.x; cf[4*i+1] = v.y; cf[4*i+2] = v.z; cf[4*i+3] = v.w;
        }
        size_t rb = (size_t)(row0 + r) * NN;

        float E1 = 0.f, F1 = 0.f, G1 = 0.f, H1 = 0.f;
        float E2 = 0.f, F2 = 0.f, G2 = 0.f, H2 = 0.f;
        #pragma unroll
        for (int j = 0; j < 8; j++) {
            E1 += cf[j]      * b1[j];      E2 += cf[j]      * b2[j];
            F1 += cf[8 + j]  * b1[8 + j];  F2 += cf[8 + j]  * b2[8 + j];
            G1 += cf[16 + j] * b1[16 + j]; G2 += cf[16 + j] * b2[16 + j];
            H1 += cf[24 + j] * b1[24 + j]; H2 += cf[24 + j] * b2[24 + j];
        }
        float P1 = E1 + F1, Q1 = E1 - F1, R1 = G1 + H1, S1 = G1 - H1;
        float P2 = E2 + F2, Q2 = E2 - F2, R2 = G2 + H2, S2 = G2 - H2;

        *(float2*)(y + rb + n1)  = make_float2(P1 + R1, P2 + R2);
        *(float2*)(y + rb + np1) = make_float2(Q1 + S1, Q2 + S2);
        y[rb + nm1]   = Q1 - S1;     // idx==0: dup of np1.x (S1==0), benign
        y[rb + nm2]   = Q2 - S2;
        y[rb + nrev1] = P1 - R1;     // idx==0: dup of y[n1=0] (R1==0), benign
        y[rb + nrev2] = P2 - R2;

        if (idx == 0) {   // outputs n=2048, 6144
            float da = 0.f, db = 0.f;
            #pragma unroll
            for (int j = 0; j < 8; j++) {
                float sg = (j & 1) ? -1.f : 1.f;
                da += sg * cf[j];        // A_{2j} * (-1)^j
                db += sg * cf[24 + j];   // B_{2j+1} * (-1)^j
            }
            y[rb + QN]     = da + db;
            y[rb + 3 * QN] = da - db;
        }
    }
}

// ---------------------------------------------------------------------------
extern "C" void kernel_launch(void* const* d_in, const int* in_sizes, int n_in,
                              void* d_out, int out_size) {
    const float* x  = (const float*)d_in[0];
    const float* wr = (const float*)d_in[1];
    const float* wi = (const float*)d_in[2];
    float*       y  = (float*)d_out;

    init_basis<<<(QN * 32 + 255) / 256, 256>>>();
    init_wr<<<(MODES * 4096 + 255) / 256, 256>>>(wr);
    init_wi<<<(MODES * 4096 + 255) / 256, 256>>>(wi);
    fwd_dft<<<dim3(ROWS / 64, KSPL), 64>>>(x);          // 4th launch -> profiled
    reduce_cs<<<(ROWS * 32 + 255) / 256, 256>>>(x);
    mix<<<dim3(MODES, 16), 256>>>();
    inv_dft<<<dim3(QN / 512, ROWS / 64), 256>>>(y);
}

// round 9
// speedup vs baseline: 1.0182x; 1.0182x over previous
#include <cuda_runtime.h>
#include <math.h>

#define NN    8192
#define HN    4096
#define QN    2048
#define MODES 16
#define ROWS  4096          /* BATCH*CH */
#define KSPL  16            /* forward m-splits */
#define MSPL  128           /* m per split = QN/KSPL */

/* fwd combo smem: [cls][m][row], row-stride T, class-stride S (floats) */
#define CMB_T 68            /* 64 rows + pad; T mod 32 = 4, T mod 4 = 0 */
#define CMB_S 2184          /* 32*68+8;      S mod 32 = 8, S mod 4 = 0 */

// Scratch (__device__ globals: allocation-free rule)
__device__ float g_FBf[QN*32];             // fwd basis, grouped, x0.5 at m=0
__device__ float g_FBi[QN*32];             // inv basis, grouped
__device__ float g_partial[KSPL*ROWS*32];  // fwd partial sums (8 MB)
__device__ float g_CS[ROWS*32];            // reduced fwd sums (+boundary)
__device__ float g_C2[ROWS*32];            // irfft coefs, grouped A/B
__device__ float g_WrT[MODES*4096];        // weights transposed: [k][i*64+o]
__device__ float g_WiT[MODES*4096];

// Grouped column layout c' = 0..31:
//   j = c'&7, odd = (c'>>3)&1, k = 2j+odd
//   c' 0..7: cos even k   8..15: cos odd   16..23: sin even   24..31: sin odd
__global__ void init_basis() {
    int idx = blockIdx.x * blockDim.x + threadIdx.x;
    if (idx >= QN * 32) return;
    int m = idx >> 5, c = idx & 31;
    int j = c & 7;
    int kk = 2 * j + ((c >> 3) & 1);
    int t = (kk * m) & (NN - 1);
    float a = (float)t * (1.0f / (float)HN);
    float v = (c < 16) ? cospif(a) : sinpif(a);
    g_FBi[idx] = v;
    g_FBf[idx] = (m == 0) ? 0.5f * v : v;   // m=0 quartet double-counts x[0],x[4096]
}
__global__ void init_wr(const float* __restrict__ wr) {
    int idx = blockIdx.x * blockDim.x + threadIdx.x;
    if (idx >= MODES * 4096) return;
    g_WrT[(idx & 15) * 4096 + (idx >> 4)] = wr[idx];
}
__global__ void init_wi(const float* __restrict__ wi) {
    int idx = blockIdx.x * blockDim.x + threadIdx.x;
    if (idx >= MODES * 4096) return;
    g_WiT[(idx & 15) * 4096 + (idx >> 4)] = wi[idx];
}

// ---------------------------------------------------------------------------
// Forward (folded): CS[row][c'] = sum_m combo_{cls}[row][m] * FBf[m][c']
// 64 rows/block, 128 threads, thread tile 4r x 4c (the 92.9-era structure).
// Inner: 2x LDS.128 + 16 FFMA. KSPL=16 -> 1024 blocks for occupancy.
// Quartet {m, 4096-m, 4096+m, (8192-m)&8191} -> 4 class combos.
// ---------------------------------------------------------------------------
__global__ __launch_bounds__(128) void fwd_dft(const float* __restrict__ x) {
    __shared__ float  cmb[4 * CMB_S];     // 34.9 KB
    __shared__ float4 bs[32][8];          // 4 KB

    const int tid  = threadIdx.x;
    const int row0 = blockIdx.x * 64;
    const int ms0  = blockIdx.y * MSPL;
    const int tr   = tid >> 3;            // 0..15 -> rows 4*tr..4*tr+3
    const int tc   = tid & 7;             // 0..7  -> cols 4*tc..4*tc+3
    const int cls  = tc >> 1;             // 0..3

    float acc[4][4];
    #pragma unroll
    for (int j = 0; j < 4; j++)
        #pragma unroll
        for (int q = 0; q < 4; q++) acc[j][q] = 0.f;

    for (int ch = 0; ch < 4; ch++) {
        const int m0 = ms0 + ch * 32;

        // stage combos: thread (row, g) covers m = g + 8*jj; conflict-free STS
        #pragma unroll
        for (int i = 0; i < 4; i++) {
            int q   = tid + i * 128;
            int row = q >> 3;
            int g   = q & 7;
            const float* xr = x + (size_t)(row0 + row) * NN;
            #pragma unroll
            for (int jj = 0; jj < 4; jj++) {
                int mi = g + 8 * jj;
                int mm = m0 + mi;
                float v0 = xr[mm];
                float v1 = xr[HN - mm];
                float v2 = xr[HN + mm];
                float v3 = xr[(NN - mm) & (NN - 1)];
                float p = v0 + v3, q2 = v0 - v3;
                float r = v1 + v2, s  = v2 - v1;
                float* base = cmb + mi * CMB_T + row;
                base[0 * CMB_S] = p + r;    // even-cos
                base[1 * CMB_S] = p - r;    // odd-cos
                base[2 * CMB_S] = q2 + s;   // even-sin
                base[3 * CMB_S] = q2 - s;   // odd-sin
            }
        }
        // stage basis tile (32 m x 32 c)
        #pragma unroll
        for (int i = 0; i < 2; i++) {
            int q  = tid + i * 128;
            int k  = q >> 3;
            int cq = q & 7;
            bs[k][cq] = *(const float4*)(g_FBf + (size_t)(m0 + k) * 32 + 4 * cq);
        }
        __syncthreads();

        const float* cbase = cmb + cls * CMB_S + 4 * tr;
        #pragma unroll
        for (int m = 0; m < 32; m++) {
            float4 xv = *(const float4*)(cbase + m * CMB_T);  // rows 4tr..4tr+3
            float4 bv = bs[m][tc];
            acc[0][0] += xv.x * bv.x; acc[0][1] += xv.x * bv.y;
            acc[0][2] += xv.x * bv.z; acc[0][3] += xv.x * bv.w;
            acc[1][0] += xv.y * bv.x; acc[1][1] += xv.y * bv.y;
            acc[1][2] += xv.y * bv.z; acc[1][3] += xv.y * bv.w;
            acc[2][0] += xv.z * bv.x; acc[2][1] += xv.z * bv.y;
            acc[2][2] += xv.z * bv.z; acc[2][3] += xv.z * bv.w;
            acc[3][0] += xv.w * bv.x; acc[3][1] += xv.w * bv.y;
            acc[3][2] += xv.w * bv.z; acc[3][3] += xv.w * bv.w;
        }
        __syncthreads();
    }

    #pragma unroll
    for (int j = 0; j < 4; j++) {
        int rg = row0 + 4 * tr + j;
        float4 v = make_float4(acc[j][0], acc[j][1], acc[j][2], acc[j][3]);
        *(float4*)(g_partial + ((size_t)blockIdx.y * ROWS + rg) * 32 + 4 * tc) = v;
    }
}

// ---------------------------------------------------------------------------
// Reduce K-splits + m=2048 boundary term. Fully coalesced.
// ---------------------------------------------------------------------------
__global__ __launch_bounds__(256) void reduce_cs(const float* __restrict__ x) {
    int q = blockIdx.x * blockDim.x + threadIdx.x;
    if (q >= ROWS * 32) return;
    int row = q >> 5, c = q & 31;
    float s = 0.f;
    #pragma unroll
    for (int ks = 0; ks < KSPL; ks++)
        s += g_partial[(size_t)ks * ROWS * 32 + q];
    float xa = x[(size_t)row * NN + QN];
    float xb = x[(size_t)row * NN + 3 * QN];
    int j = c & 7;
    float sg = (j & 1) ? -1.f : 1.f;
    if (c < 8)        s += (xa + xb) * sg;
    else if (c >= 24) s += (xa - xb) * sg;
    g_CS[q] = s;
}

// ---------------------------------------------------------------------------
// Mix: grid (16 k, 16 bg), 256 thr. Weights read directly from transposed
// copy (coalesced LDG, L1/L2-resident) -- no smem staging phase.
// ---------------------------------------------------------------------------
__global__ __launch_bounds__(256) void mix() {
    __shared__ float sXc[256], sXs[256];
    const int k   = blockIdx.x;
    const int bg  = blockIdx.y;
    const int tid = threadIdx.x;

    const int cA = (k & 1) ? 8 + (k >> 1) : (k >> 1);
    const int cS = cA + 16;

    {   // (b_local = tid>>6, i = tid&63)
        int row = (bg * 4 + (tid >> 6)) * 64 + (tid & 63);
        sXc[tid] = g_CS[(size_t)row * 32 + cA];
        sXs[tid] = g_CS[(size_t)row * 32 + cS];
    }
    __syncthreads();

    const int o  = tid & 63;
    const int bl = tid >> 6;
    const float* wrk = g_WrT + (size_t)k * 4096 + o;
    const float* wik = g_WiT + (size_t)k * 4096 + o;

    float cre = 0.f, cim = 0.f;
    #pragma unroll 8
    for (int i = 0; i < 64; i++) {
        float a   = sXc[bl * 64 + i];        // broadcast LDS
        float s   = sXs[bl * 64 + i];
        float wre = __ldg(wrk + i * 64);     // coalesced across lanes
        float wim = __ldg(wik + i * 64);
        cre += a * wre + s * wim;
        cim += a * wim - s * wre;
    }
    const float invN = 1.0f / (float)NN;
    float A  = (k == 0 ? cre : 2.f * cre) * invN;
    float Bc = (k == 0 ? 0.f : -2.f * cim * invN);
    int rowo = (bg * 4 + bl) * 64 + o;
    g_C2[(size_t)rowo * 32 + cA] = A;
    g_C2[(size_t)rowo * 32 + cS] = Bc;
}

// ---------------------------------------------------------------------------
// Inverse (folded): thread owns adjacent n1=2*idx, n2=n1+1 (basis 64 regs).
// 128 thr/block, 32 rows/block -> 1024 blocks (occupancy). Coef float4s are
// consumed immediately into 4 group-accumulators (no cf[32] array -> ~90 regs).
// Ascending pairs [n1,n2], [np1,np1+1] 8B-aligned -> STG.64; descending
// mirrors odd-based -> scalar STG.32. n=0 wraps are exact duplicates.
// ---------------------------------------------------------------------------
__global__ __launch_bounds__(128) void inv_dft(float* __restrict__ y) {
    __shared__ float sC[32 * 32];
    const int tid  = threadIdx.x;
    const int row0 = blockIdx.y * 32;
    const int idx  = blockIdx.x * 128 + tid;    // 0..1023
    const int n1   = 2 * idx;
    const int n2   = n1 + 1;

    #pragma unroll
    for (int i = 0; i < 2; i++) {
        int q = tid + i * 128;
        *(float4*)(sC + 4 * q) = *(const float4*)(g_C2 + (size_t)row0 * 32 + 4 * q);
    }

    float b1[32], b2[32];
    #pragma unroll
    for (int i = 0; i < 8; i++) {
        float4 v = *(const float4*)(g_FBi + (size_t)n1 * 32 + 4 * i);
        b1[4*i+0] = v.x; b1[4*i+1] = v.y; b1[4*i+2] = v.z; b1[4*i+3] = v.w;
        float4 u = *(const float4*)(g_FBi + (size_t)n2 * 32 + 4 * i);
        b2[4*i+0] = u.x; b2[4*i+1] = u.y; b2[4*i+2] = u.z; b2[4*i+3] = u.w;
    }
    __syncthreads();

    const int np1   = HN + n1;                  // even: STG.64 ok
    const int nm1   = HN - n1;
    const int nm2   = HN - n2;                  // odd
    const int nrev1 = (NN - n1) & (NN - 1);     // 0 when idx==0 (dup, benign)
    const int nrev2 = NN - n2;                  // odd

    for (int r = 0; r < 32; r++) {
        const float* cp = sC + r * 32;
        // group accumulators: a[0]=E (cos-even), a[1]=F (cos-odd),
        //                     a[2]=G (sin-even), a[3]=H (sin-odd)
        float a1[4] = {0.f, 0.f, 0.f, 0.f};
        float a2[4] = {0.f, 0.f, 0.f, 0.f};
        #pragma unroll
        for (int i = 0; i < 8; i++) {
            float4 v = *(const float4*)(cp + 4 * i);   // broadcast LDS.128
            int g = i >> 1;
            a1[g] += v.x * b1[4*i] + v.y * b1[4*i+1] + v.z * b1[4*i+2] + v.w * b1[4*i+3];
            a2[g] += v.x * b2[4*i] + v.y * b2[4*i+1] + v.z * b2[4*i+2] + v.w * b2[4*i+3];
        }
        float P1 = a1[0] + a1[1], Q1 = a1[0] - a1[1];
        float R1 = a1[2] + a1[3], S1 = a1[2] - a1[3];
        float P2 = a2[0] + a2[1], Q2 = a2[0] - a2[1];
        float R2 = a2[2] + a2[3], S2 = a2[2] - a2[3];
        size_t rb = (size_t)(row0 + r) * NN;

        *(float2*)(y + rb + n1)  = make_float2(P1 + R1, P2 + R2);
        *(float2*)(y + rb + np1) = make_float2(Q1 + S1, Q2 + S2);
        y[rb + nm1]   = Q1 - S1;     // idx==0: dup of np1.x (S1==0), benign
        y[rb + nm2]   = Q2 - S2;
        y[rb + nrev1] = P1 - R1;     // idx==0: dup of y[0] (R1==0), benign
        y[rb + nrev2] = P2 - R2;

        if (idx == 0) {   // outputs n=2048, 6144
            float da = 0.f, db = 0.f;
            #pragma unroll
            for (int i = 0; i < 8; i++) {
                float sg = (i & 1) ? -1.f : 1.f;
                da += sg * cp[i];        // A_{2j} * (-1)^j
                db += sg * cp[24 + i];   // B_{2j+1} * (-1)^j
            }
            y[rb + QN]     = da + db;
            y[rb + 3 * QN] = da - db;
        }
    }
}

// ---------------------------------------------------------------------------
extern "C" void kernel_launch(void* const* d_in, const int* in_sizes, int n_in,
                              void* d_out, int out_size) {
    const float* x  = (const float*)d_in[0];
    const float* wr = (const float*)d_in[1];
    const float* wi = (const float*)d_in[2];
    float*       y  = (float*)d_out;

    init_basis<<<(QN * 32 + 255) / 256, 256>>>();
    init_wr<<<(MODES * 4096 + 255) / 256, 256>>>(wr);
    init_wi<<<(MODES * 4096 + 255) / 256, 256>>>(wi);
    fwd_dft<<<dim3(ROWS / 64, KSPL), 128>>>(x);          // 4th launch -> profiled
    reduce_cs<<<(ROWS * 32 + 255) / 256, 256>>>(x);
    mix<<<dim3(MODES, 16), 256>>>();
    inv_dft<<<dim3(QN / 256, ROWS / 32), 128>>>(y);
}

// round 10
// speedup vs baseline: 1.0677x; 1.0486x over previous
#include <cuda_runtime.h>
#include <math.h>

#define NN    8192
#define HN    4096
#define QN    2048
#define MODES 16
#define ROWS  4096          /* BATCH*CH */
#define KSPL  16            /* forward m-splits */
#define MSPL  128           /* m per split = QN/KSPL */

/* fwd combo smem: [cls][m][row], row-stride T, class-stride S (floats) */
#define CMB_T 68            /* 64 rows + pad; T mod 32 = 4, T mod 4 = 0 */
#define CMB_S 2184          /* 32*68+8;      S mod 32 = 8, S mod 4 = 0 */

// Scratch (__device__ globals: allocation-free rule)
__device__ float g_FBf[QN*32];             // fwd basis, grouped, x0.5 at m=0
__device__ float g_FBi[QN*32];             // inv basis, grouped
__device__ float g_partial[KSPL*ROWS*32];  // fwd partial sums (8 MB)
__device__ float g_CS[ROWS*32];            // reduced fwd sums (+boundary)
__device__ float g_C2[ROWS*32];            // irfft coefs, grouped A/B
__device__ float g_WrT[MODES*4096];        // weights transposed: [k][i*64+o]
__device__ float g_WiT[MODES*4096];

// Grouped column layout c' = 0..31:
//   j = c'&7, odd = (c'>>3)&1, k = 2j+odd
//   c' 0..7: cos even k   8..15: cos odd   16..23: sin even   24..31: sin odd
__global__ void init_tables(const float* __restrict__ wr,
                            const float* __restrict__ wi) {
    int idx = blockIdx.x * blockDim.x + threadIdx.x;
    if (idx >= QN * 32) return;   // 65536 == basis entries == weight entries
    {   // basis
        int m = idx >> 5, c = idx & 31;
        int j = c & 7;
        int kk = 2 * j + ((c >> 3) & 1);
        int t = (kk * m) & (NN - 1);
        float a = (float)t * (1.0f / (float)HN);
        float v = (c < 16) ? cospif(a) : sinpif(a);
        g_FBi[idx] = v;
        g_FBf[idx] = (m == 0) ? 0.5f * v : v;  // m=0 quartet double-counts x[0],x[4096]
    }
    {   // weight transpose: wr[(i*64+o)*16+k] -> g_WrT[k][i*64+o]
        int io = idx >> 4, k = idx & 15;
        g_WrT[k * 4096 + io] = wr[idx];
        g_WiT[k * 4096 + io] = wi[idx];
    }
}

// ---------------------------------------------------------------------------
// Forward (folded): CS[row][c'] = sum_m combo_{cls}[row][m] * FBf[m][c']
// 64 rows/block, 128 threads, thread tile 4r x 4c. Inner: 2x LDS.128 + 16 FFMA.
// Quartet {m, 4096-m, 4096+m, (8192-m)&8191} -> 4 class combos.
// ---------------------------------------------------------------------------
__global__ __launch_bounds__(128) void fwd_dft(const float* __restrict__ x) {
    __shared__ float  cmb[4 * CMB_S];     // 34.9 KB
    __shared__ float4 bs[32][8];          // 4 KB

    const int tid  = threadIdx.x;
    const int row0 = blockIdx.x * 64;
    const int ms0  = blockIdx.y * MSPL;
    const int tr   = tid >> 3;            // 0..15 -> rows 4*tr..4*tr+3
    const int tc   = tid & 7;             // 0..7  -> cols 4*tc..4*tc+3
    const int cls  = tc >> 1;             // 0..3

    float acc[4][4];
    #pragma unroll
    for (int j = 0; j < 4; j++)
        #pragma unroll
        for (int q = 0; q < 4; q++) acc[j][q] = 0.f;

    for (int ch = 0; ch < 4; ch++) {
        const int m0 = ms0 + ch * 32;

        // stage combos: thread (row, g) covers m = g + 8*jj; conflict-free STS
        #pragma unroll
        for (int i = 0; i < 4; i++) {
            int q   = tid + i * 128;
            int row = q >> 3;
            int g   = q & 7;
            const float* xr = x + (size_t)(row0 + row) * NN;
            #pragma unroll
            for (int jj = 0; jj < 4; jj++) {
                int mi = g + 8 * jj;
                int mm = m0 + mi;
                float v0 = xr[mm];
                float v1 = xr[HN - mm];
                float v2 = xr[HN + mm];
                float v3 = xr[(NN - mm) & (NN - 1)];
                float p = v0 + v3, q2 = v0 - v3;
                float r = v1 + v2, s  = v2 - v1;
                float* base = cmb + mi * CMB_T + row;
                base[0 * CMB_S] = p + r;    // even-cos
                base[1 * CMB_S] = p - r;    // odd-cos
                base[2 * CMB_S] = q2 + s;   // even-sin
                base[3 * CMB_S] = q2 - s;   // odd-sin
            }
        }
        // stage basis tile (32 m x 32 c)
        #pragma unroll
        for (int i = 0; i < 2; i++) {
            int q  = tid + i * 128;
            int k  = q >> 3;
            int cq = q & 7;
            bs[k][cq] = *(const float4*)(g_FBf + (size_t)(m0 + k) * 32 + 4 * cq);
        }
        __syncthreads();

        const float* cbase = cmb + cls * CMB_S + 4 * tr;
        #pragma unroll
        for (int m = 0; m < 32; m++) {
            float4 xv = *(const float4*)(cbase + m * CMB_T);  // rows 4tr..4tr+3
            float4 bv = bs[m][tc];
            acc[0][0] += xv.x * bv.x; acc[0][1] += xv.x * bv.y;
            acc[0][2] += xv.x * bv.z; acc[0][3] += xv.x * bv.w;
            acc[1][0] += xv.y * bv.x; acc[1][1] += xv.y * bv.y;
            acc[1][2] += xv.y * bv.z; acc[1][3] += xv.y * bv.w;
            acc[2][0] += xv.z * bv.x; acc[2][1] += xv.z * bv.y;
            acc[2][2] += xv.z * bv.z; acc[2][3] += xv.z * bv.w;
            acc[3][0] += xv.w * bv.x; acc[3][1] += xv.w * bv.y;
            acc[3][2] += xv.w * bv.z; acc[3][3] += xv.w * bv.w;
        }
        __syncthreads();
    }

    #pragma unroll
    for (int j = 0; j < 4; j++) {
        int rg = row0 + 4 * tr + j;
        float4 v = make_float4(acc[j][0], acc[j][1], acc[j][2], acc[j][3]);
        *(float4*)(g_partial + ((size_t)blockIdx.y * ROWS + rg) * 32 + 4 * tc) = v;
    }
}

// ---------------------------------------------------------------------------
// Reduce K-splits + m=2048 boundary term. Fully coalesced.
// ---------------------------------------------------------------------------
__global__ __launch_bounds__(256) void reduce_cs(const float* __restrict__ x) {
    int q = blockIdx.x * blockDim.x + threadIdx.x;
    if (q >= ROWS * 32) return;
    int row = q >> 5, c = q & 31;
    float s = 0.f;
    #pragma unroll
    for (int ks = 0; ks < KSPL; ks++)
        s += g_partial[(size_t)ks * ROWS * 32 + q];
    float xa = x[(size_t)row * NN + QN];
    float xb = x[(size_t)row * NN + 3 * QN];
    int j = c & 7;
    float sg = (j & 1) ? -1.f : 1.f;
    if (c < 8)        s += (xa + xb) * sg;
    else if (c >= 24) s += (xa - xb) * sg;
    g_CS[q] = s;
}

// ---------------------------------------------------------------------------
// Mix: grid (16 k, 16 bg), 256 thr. Weights read directly from transposed
// copy (coalesced LDG, L1/L2-resident) -- no smem staging phase.
// ---------------------------------------------------------------------------
__global__ __launch_bounds__(256) void mix() {
    __shared__ float sXc[256], sXs[256];
    const int k   = blockIdx.x;
    const int bg  = blockIdx.y;
    const int tid = threadIdx.x;

    const int cA = (k & 1) ? 8 + (k >> 1) : (k >> 1);
    const int cS = cA + 16;

    {   // (b_local = tid>>6, i = tid&63)
        int row = (bg * 4 + (tid >> 6)) * 64 + (tid & 63);
        sXc[tid] = g_CS[(size_t)row * 32 + cA];
        sXs[tid] = g_CS[(size_t)row * 32 + cS];
    }
    __syncthreads();

    const int o  = tid & 63;
    const int bl = tid >> 6;
    const float* wrk = g_WrT + (size_t)k * 4096 + o;
    const float* wik = g_WiT + (size_t)k * 4096 + o;

    float cre = 0.f, cim = 0.f;
    #pragma unroll 8
    for (int i = 0; i < 64; i++) {
        float a   = sXc[bl * 64 + i];        // broadcast LDS
        float s   = sXs[bl * 64 + i];
        float wre = __ldg(wrk + i * 64);     // coalesced across lanes
        float wim = __ldg(wik + i * 64);
        cre += a * wre + s * wim;
        cim += a * wim - s * wre;
    }
    const float invN = 1.0f / (float)NN;
    float A  = (k == 0 ? cre : 2.f * cre) * invN;
    float Bc = (k == 0 ? 0.f : -2.f * cim * invN);
    int rowo = (bg * 4 + bl) * 64 + o;
    g_C2[(size_t)rowo * 32 + cA] = A;
    g_C2[(size_t)rowo * 32 + cS] = Bc;
}

// ---------------------------------------------------------------------------
// Inverse (folded): SPREAD-n mapping -- thread owns n1 = idx (0..1023) and
// n2 = n1 + 1024, so every one of the 8 scalar stores is warp-coalesced
// (lanes write 32 consecutive floats per region). Group-accumulator
// consumption keeps regs ~90. 128 thr, 32 rows/block -> 1024 blocks.
// n=0 wraps are exact duplicates (sin basis = 0); idx==0 emits n=2048/6144.
// ---------------------------------------------------------------------------
__global__ __launch_bounds__(128) void inv_dft(float* __restrict__ y) {
    __shared__ float sC[32 * 32];
    const int tid  = threadIdx.x;
    const int row0 = blockIdx.y * 32;
    const int n1   = blockIdx.x * 128 + tid;    // 0..1023
    const int n2   = n1 + 1024;                 // 1024..2047

    #pragma unroll
    for (int i = 0; i < 2; i++) {
        int q = tid + i * 128;
        *(float4*)(sC + 4 * q) = *(const float4*)(g_C2 + (size_t)row0 * 32 + 4 * q);
    }

    float b1[32], b2[32];
    #pragma unroll
    for (int i = 0; i < 8; i++) {
        float4 v = *(const float4*)(g_FBi + (size_t)n1 * 32 + 4 * i);
        b1[4*i+0] = v.x; b1[4*i+1] = v.y; b1[4*i+2] = v.z; b1[4*i+3] = v.w;
        float4 u = *(const float4*)(g_FBi + (size_t)n2 * 32 + 4 * i);
        b2[4*i+0] = u.x; b2[4*i+1] = u.y; b2[4*i+2] = u.z; b2[4*i+3] = u.w;
    }
    __syncthreads();

    const int nrev1 = (NN - n1) & (NN - 1);     // 0 when n1==0 (dup, benign)
    const int nm1   = HN - n1,  np1 = HN + n1;
    const int nrev2 = NN - n2;
    const int nm2   = HN - n2,  np2 = HN + n2;

    for (int r = 0; r < 32; r++) {
        const float* cp = sC + r * 32;
        // a[0]=E (cos-even), a[1]=F (cos-odd), a[2]=G (sin-even), a[3]=H (sin-odd)
        float a1[4] = {0.f, 0.f, 0.f, 0.f};
        float a2[4] = {0.f, 0.f, 0.f, 0.f};
        #pragma unroll
        for (int i = 0; i < 8; i++) {
            float4 v = *(const float4*)(cp + 4 * i);   // broadcast LDS.128
            int g = i >> 1;
            a1[g] += v.x * b1[4*i] + v.y * b1[4*i+1] + v.z * b1[4*i+2] + v.w * b1[4*i+3];
            a2[g] += v.x * b2[4*i] + v.y * b2[4*i+1] + v.z * b2[4*i+2] + v.w * b2[4*i+3];
        }
        float P1 = a1[0] + a1[1], Q1 = a1[0] - a1[1];
        float R1 = a1[2] + a1[3], S1 = a1[2] - a1[3];
        float P2 = a2[0] + a2[1], Q2 = a2[0] - a2[1];
        float R2 = a2[2] + a2[3], S2 = a2[2] - a2[3];
        size_t rb = (size_t)(row0 + r) * NN;

        y[rb + n1]    = P1 + R1;
        y[rb + nrev1] = P1 - R1;     // n1==0: dup of y[0] (R1==0), benign
        y[rb + nm1]   = Q1 - S1;     // n1==0: dup of np1 (S1==0), benign
        y[rb + np1]   = Q1 + S1;
        y[rb + n2]    = P2 + R2;
        y[rb + nrev2] = P2 - R2;
        y[rb + nm2]   = Q2 - S2;
        y[rb + np2]   = Q2 + S2;

        if (n1 == 0) {   // outputs n=2048, 6144
            float da = 0.f, db = 0.f;
            #pragma unroll
            for (int i = 0; i < 8; i++) {
                float sg = (i & 1) ? -1.f : 1.f;
                da += sg * cp[i];        // A_{2j} * (-1)^j
                db += sg * cp[24 + i];   // B_{2j+1} * (-1)^j
            }
            y[rb + QN]     = da + db;
            y[rb + 3 * QN] = da - db;
        }
    }
}

// ---------------------------------------------------------------------------
extern "C" void kernel_launch(void* const* d_in, const int* in_sizes, int n_in,
                              void* d_out, int out_size) {
    const float* x  = (const float*)d_in[0];
    const float* wr = (const float*)d_in[1];
    const float* wi = (const float*)d_in[2];
    float*       y  = (float*)d_out;

    init_tables<<<(QN * 32 + 255) / 256, 256>>>(wr, wi);
    fwd_dft<<<dim3(ROWS / 64, KSPL), 128>>>(x);
    reduce_cs<<<(ROWS * 32 + 255) / 256, 256>>>(x);
    mix<<<dim3(MODES, 16), 256>>>();        // 4th launch -> profiled
    inv_dft<<<dim3(QN / 2 / 128, ROWS / 32), 128>>>(y);
}

// round 11
// speedup vs baseline: 1.1979x; 1.1219x over previous
#include <cuda_runtime.h>
#include <math.h>

#define NN    8192
#define HN    4096
#define QN    2048
#define MODES 16
#define ROWS  4096          /* BATCH*CH */
#define KSPL  8             /* forward m-splits: 512 blocks = single wave */
#define MSPL  256           /* m per split = QN/KSPL */

/* fwd combo smem: [cls][m][row], row-stride T, class-stride S (floats) */
#define CMB_T 68            /* 64 rows + pad; T mod 32 = 4, T mod 4 = 0 */
#define CMB_S 2184          /* 32*68+8;      S mod 32 = 8, S mod 4 = 0 */

// Scratch (__device__ globals: allocation-free rule)
__device__ float g_FBf[QN*32];             // fwd basis, grouped, x0.5 at m=0
__device__ float g_FBi[QN*32];             // inv basis, grouped
__device__ float g_partial[KSPL*ROWS*32];  // fwd partial sums (4 MB)
__device__ float g_CS[ROWS*32];            // reduced fwd sums (+boundary)
__device__ float g_C2[ROWS*32];            // irfft coefs, grouped A/B
__device__ float g_WrT[MODES*4096];        // weights transposed: [k][i*64+o]
__device__ float g_WiT[MODES*4096];

// Grouped column layout c' = 0..31:
//   j = c'&7, odd = (c'>>3)&1, k = 2j+odd
//   c' 0..7: cos even k   8..15: cos odd   16..23: sin even   24..31: sin odd
__global__ void init_tables(const float* __restrict__ wr,
                            const float* __restrict__ wi) {
    int idx = blockIdx.x * blockDim.x + threadIdx.x;
    if (idx >= QN * 32) return;   // 65536 == basis entries == weight entries
    {   // basis
        int m = idx >> 5, c = idx & 31;
        int j = c & 7;
        int kk = 2 * j + ((c >> 3) & 1);
        int t = (kk * m) & (NN - 1);
        float a = (float)t * (1.0f / (float)HN);
        float v = (c < 16) ? cospif(a) : sinpif(a);
        g_FBi[idx] = v;
        g_FBf[idx] = (m == 0) ? 0.5f * v : v;  // m=0 quartet double-counts x[0],x[4096]
    }
    {   // weight transpose: wr[(i*64+o)*16+k] -> g_WrT[k][i*64+o]
        int io = idx >> 4, k = idx & 15;
        g_WrT[k * 4096 + io] = wr[idx];
        g_WiT[k * 4096 + io] = wi[idx];
    }
}

// ---------------------------------------------------------------------------
// Forward (folded): CS[row][c'] = sum_m combo_{cls}[row][m] * FBf[m][c']
// 64 rows/block, 128 threads, thread tile 4r x 4c. Inner: 2x LDS.128 + 16 FFMA
// with explicit register double-buffer. KSPL=8 -> 512 blocks (single wave).
// Quartet {m, 4096-m, 4096+m, (8192-m)&8191} -> 4 class combos.
// ---------------------------------------------------------------------------
__global__ __launch_bounds__(128) void fwd_dft(const float* __restrict__ x) {
    __shared__ float  cmb[4 * CMB_S];     // 34.9 KB
    __shared__ float4 bs[32][8];          // 4 KB

    const int tid  = threadIdx.x;
    const int row0 = blockIdx.x * 64;
    const int ms0  = blockIdx.y * MSPL;
    const int tr   = tid >> 3;            // 0..15 -> rows 4*tr..4*tr+3
    const int tc   = tid & 7;             // 0..7  -> cols 4*tc..4*tc+3
    const int cls  = tc >> 1;             // 0..3

    float acc[4][4];
    #pragma unroll
    for (int j = 0; j < 4; j++)
        #pragma unroll
        for (int q = 0; q < 4; q++) acc[j][q] = 0.f;

    for (int ch = 0; ch < MSPL / 32; ch++) {
        const int m0 = ms0 + ch * 32;

        // stage combos: thread (row, g) covers m = g + 8*jj; conflict-free STS
        #pragma unroll
        for (int i = 0; i < 4; i++) {
            int q   = tid + i * 128;
            int row = q >> 3;
            int g   = q & 7;
            const float* xr = x + (size_t)(row0 + row) * NN;
            #pragma unroll
            for (int jj = 0; jj < 4; jj++) {
                int mi = g + 8 * jj;
                int mm = m0 + mi;
                float v0 = xr[mm];
                float v1 = xr[HN - mm];
                float v2 = xr[HN + mm];
                float v3 = xr[(NN - mm) & (NN - 1)];
                float p = v0 + v3, q2 = v0 - v3;
                float r = v1 + v2, s  = v2 - v1;
                float* base = cmb + mi * CMB_T + row;
                base[0 * CMB_S] = p + r;    // even-cos
                base[1 * CMB_S] = p - r;    // odd-cos
                base[2 * CMB_S] = q2 + s;   // even-sin
                base[3 * CMB_S] = q2 - s;   // odd-sin
            }
        }
        // stage basis tile (32 m x 32 c)
        #pragma unroll
        for (int i = 0; i < 2; i++) {
            int q  = tid + i * 128;
            int k  = q >> 3;
            int cq = q & 7;
            bs[k][cq] = *(const float4*)(g_FBf + (size_t)(m0 + k) * 32 + 4 * cq);
        }
        __syncthreads();

        const float* cbase = cmb + cls * CMB_S + 4 * tr;
        float4 xv = *(const float4*)(cbase);
        float4 bv = bs[0][tc];
        #pragma unroll
        for (int m = 0; m < 32; m++) {
            float4 xvn, bvn;
            if (m < 31) {                       // register double-buffer
                xvn = *(const float4*)(cbase + (m + 1) * CMB_T);
                bvn = bs[m + 1][tc];
            }
            acc[0][0] += xv.x * bv.x; acc[0][1] += xv.x * bv.y;
            acc[0][2] += xv.x * bv.z; acc[0][3] += xv.x * bv.w;
            acc[1][0] += xv.y * bv.x; acc[1][1] += xv.y * bv.y;
            acc[1][2] += xv.y * bv.z; acc[1][3] += xv.y * bv.w;
            acc[2][0] += xv.z * bv.x; acc[2][1] += xv.z * bv.y;
            acc[2][2] += xv.z * bv.z; acc[2][3] += xv.z * bv.w;
            acc[3][0] += xv.w * bv.x; acc[3][1] += xv.w * bv.y;
            acc[3][2] += xv.w * bv.z; acc[3][3] += xv.w * bv.w;
            xv = xvn; bv = bvn;
        }
        __syncthreads();
    }

    #pragma unroll
    for (int j = 0; j < 4; j++) {
        int rg = row0 + 4 * tr + j;
        float4 v = make_float4(acc[j][0], acc[j][1], acc[j][2], acc[j][3]);
        *(float4*)(g_partial + ((size_t)blockIdx.y * ROWS + rg) * 32 + 4 * tc) = v;
    }
}

// ---------------------------------------------------------------------------
// Reduce K-splits + m=2048 boundary term. Fully coalesced.
// ---------------------------------------------------------------------------
__global__ __launch_bounds__(256) void reduce_cs(const float* __restrict__ x) {
    int q = blockIdx.x * blockDim.x + threadIdx.x;
    if (q >= ROWS * 32) return;
    int row = q >> 5, c = q & 31;
    float s = 0.f;
    #pragma unroll
    for (int ks = 0; ks < KSPL; ks++)
        s += g_partial[(size_t)ks * ROWS * 32 + q];
    float xa = x[(size_t)row * NN + QN];
    float xb = x[(size_t)row * NN + 3 * QN];
    int j = c & 7;
    float sg = (j & 1) ? -1.f : 1.f;
    if (c < 8)        s += (xa + xb) * sg;
    else if (c >= 24) s += (xa - xb) * sg;
    g_CS[q] = s;
}

// ---------------------------------------------------------------------------
// Mix (R6-proven): grid (16 k, 16 bg), 256 thr. Weights staged into smem with
// bulk coalesced float4 loads (high MLP), inner loop LDS-only.
// ---------------------------------------------------------------------------
__global__ __launch_bounds__(256) void mix() {
    __shared__ float sWr[64 * 64];
    __shared__ float sWi[64 * 64];
    __shared__ float sXc[256], sXs[256];
    const int k   = blockIdx.x;
    const int bg  = blockIdx.y;
    const int tid = threadIdx.x;

    const int cA = (k & 1) ? 8 + (k >> 1) : (k >> 1);
    const int cS = cA + 16;

    const float* wrk = g_WrT + (size_t)k * 4096;
    const float* wik = g_WiT + (size_t)k * 4096;
    #pragma unroll
    for (int i = 0; i < 4; i++) {
        int q = tid + i * 256;
        ((float4*)sWr)[q] = ((const float4*)wrk)[q];
        ((float4*)sWi)[q] = ((const float4*)wik)[q];
    }
    {   // (b_local = tid>>6, i = tid&63)
        int row = (bg * 4 + (tid >> 6)) * 64 + (tid & 63);
        sXc[tid] = g_CS[(size_t)row * 32 + cA];
        sXs[tid] = g_CS[(size_t)row * 32 + cS];
    }
    __syncthreads();

    const int o  = tid & 63;
    const int bl = tid >> 6;
    float cre = 0.f, cim = 0.f;
    #pragma unroll 8
    for (int i = 0; i < 64; i++) {
        float a   = sXc[bl * 64 + i];
        float s   = sXs[bl * 64 + i];
        float wre = sWr[i * 64 + o];
        float wim = sWi[i * 64 + o];
        cre += a * wre + s * wim;
        cim += a * wim - s * wre;
    }
    const float invN = 1.0f / (float)NN;
    float A  = (k == 0 ? cre : 2.f * cre) * invN;
    float Bc = (k == 0 ? 0.f : -2.f * cim * invN);
    int rowo = (bg * 4 + bl) * 64 + o;
    g_C2[(size_t)rowo * 32 + cA] = A;
    g_C2[(size_t)rowo * 32 + cS] = Bc;
}

// ---------------------------------------------------------------------------
// Inverse (folded): SPREAD-n -- thread owns n1 = idx (0..1023), n2 = n1+1024;
// all 8 scalar stores warp-coalesced (1 transaction each). Group-accumulator
// consumption keeps regs ~90. 128 thr, 32 rows/block -> 1024 blocks.
// n=0 wraps are exact duplicates (sin basis = 0); n1==0 emits n=2048/6144.
// ---------------------------------------------------------------------------
__global__ __launch_bounds__(128) void inv_dft(float* __restrict__ y) {
    __shared__ float sC[32 * 32];
    const int tid  = threadIdx.x;
    const int row0 = blockIdx.y * 32;
    const int n1   = blockIdx.x * 128 + tid;    // 0..1023
    const int n2   = n1 + 1024;                 // 1024..2047

    #pragma unroll
    for (int i = 0; i < 2; i++) {
        int q = tid + i * 128;
        *(float4*)(sC + 4 * q) = *(const float4*)(g_C2 + (size_t)row0 * 32 + 4 * q);
    }

    float b1[32], b2[32];
    #pragma unroll
    for (int i = 0; i < 8; i++) {
        float4 v = *(const float4*)(g_FBi + (size_t)n1 * 32 + 4 * i);
        b1[4*i+0] = v.x; b1[4*i+1] = v.y; b1[4*i+2] = v.z; b1[4*i+3] = v.w;
        float4 u = *(const float4*)(g_FBi + (size_t)n2 * 32 + 4 * i);
        b2[4*i+0] = u.x; b2[4*i+1] = u.y; b2[4*i+2] = u.z; b2[4*i+3] = u.w;
    }
    __syncthreads();

    const int nrev1 = (NN - n1) & (NN - 1);     // 0 when n1==0 (dup, benign)
    const int nm1   = HN - n1,  np1 = HN + n1;
    const int nrev2 = NN - n2;
    const int nm2   = HN - n2,  np2 = HN + n2;

    for (int r = 0; r < 32; r++) {
        const float* cp = sC + r * 32;
        // a[0]=E (cos-even), a[1]=F (cos-odd), a[2]=G (sin-even), a[3]=H (sin-odd)
        float a1[4] = {0.f, 0.f, 0.f, 0.f};
        float a2[4] = {0.f, 0.f, 0.f, 0.f};
        #pragma unroll
        for (int i = 0; i < 8; i++) {
            float4 v = *(const float4*)(cp + 4 * i);   // broadcast LDS.128
            int g = i >> 1;
            a1[g] += v.x * b1[4*i] + v.y * b1[4*i+1] + v.z * b1[4*i+2] + v.w * b1[4*i+3];
            a2[g] += v.x * b2[4*i] + v.y * b2[4*i+1] + v.z * b2[4*i+2] + v.w * b2[4*i+3];
        }
        float P1 = a1[0] + a1[1], Q1 = a1[0] - a1[1];
        float R1 = a1[2] + a1[3], S1 = a1[2] - a1[3];
        float P2 = a2[0] + a2[1], Q2 = a2[0] - a2[1];
        float R2 = a2[2] + a2[3], S2 = a2[2] - a2[3];
        size_t rb = (size_t)(row0 + r) * NN;

        y[rb + n1]    = P1 + R1;
        y[rb + nrev1] = P1 - R1;     // n1==0: dup of y[0] (R1==0), benign
        y[rb + nm1]   = Q1 - S1;     // n1==0: dup of np1 (S1==0), benign
        y[rb + np1]   = Q1 + S1;
        y[rb + n2]    = P2 + R2;
        y[rb + nrev2] = P2 - R2;
        y[rb + nm2]   = Q2 - S2;
        y[rb + np2]   = Q2 + S2;

        if (n1 == 0) {   // outputs n=2048, 6144
            float da = 0.f, db = 0.f;
            #pragma unroll
            for (int i = 0; i < 8; i++) {
                float sg = (i & 1) ? -1.f : 1.f;
                da += sg * cp[i];        // A_{2j} * (-1)^j
                db += sg * cp[24 + i];   // B_{2j+1} * (-1)^j
            }
            y[rb + QN]     = da + db;
            y[rb + 3 * QN] = da - db;
        }
    }
}

// ---------------------------------------------------------------------------
extern "C" void kernel_launch(void* const* d_in, const int* in_sizes, int n_in,
                              void* d_out, int out_size) {
    const float* x  = (const float*)d_in[0];
    const float* wr = (const float*)d_in[1];
    const float* wi = (const float*)d_in[2];
    float*       y  = (float*)d_out;

    init_tables<<<(QN * 32 + 255) / 256, 256>>>(wr, wi);
    fwd_dft<<<dim3(ROWS / 64, KSPL), 128>>>(x);
    reduce_cs<<<(ROWS * 32 + 255) / 256, 256>>>(x);
    mix<<<dim3(MODES, 16), 256>>>();        // 4th launch -> profiled
    inv_dft<<<dim3(QN / 2 / 128, ROWS / 32), 128>>>(y);
}